// round 6
// baseline (speedup 1.0000x reference)
#include <cuda_runtime.h>

#define BB 8
#define TT 512
#define CC 128
#define HH 1024
#define GBLK 148
#define GW 7

typedef unsigned long long ull;

// ---------------- f32x2 helpers ----------------
__device__ __forceinline__ ull dup2(float x)
{
    ull r;
    asm("mov.b64 %0, {%1, %1};" : "=l"(r) : "f"(x));
    return r;
}
__device__ __forceinline__ ull pack2(float lo, float hi)
{
    ull r;
    asm("mov.b64 %0, {%1, %2};" : "=l"(r) : "f"(lo), "f"(hi));
    return r;
}
__device__ __forceinline__ ull ffma2(ull a, ull b, ull c)
{
    ull d;
    asm("fma.rn.f32x2 %0, %1, %2, %3;" : "=l"(d) : "l"(a), "l"(b), "l"(c));
    return d;
}
__device__ __forceinline__ float2 unpk2(ull v)
{
    float2 f;
    asm("mov.b64 {%0, %1}, %2;" : "=f"(f.x), "=f"(f.y) : "l"(v));
    return f;
}

// ---------------- static scratch ----------------
__device__ float g_xg[BB * TT * 3 * HH];
__device__ float g_h[2][BB * HH];
__device__ float g_emb2[BB * CC * TT * 8];
__device__ float g_x3[BB * CC * TT * 8];
__device__ float g_e3x[BB * CC * TT * 16];
__device__ float g_x2[BB * CC * TT * 16];
__device__ float g_e2x[BB * CC * TT * 32];
__device__ float g_x1[BB * CC * TT * 32];
__device__ float g_e1x[BB * CC * TT * 64];
__device__ float g_wtT[3 * CC * CC];
__device__ unsigned g_bar_count;
__device__ unsigned g_bar_gen;

// ---------------- grid barrier (all blocks resident) ----------------
__device__ __forceinline__ void grid_barrier()
{
    __syncthreads();
    if (threadIdx.x == 0) {
        volatile unsigned* genp = &g_bar_gen;
        unsigned g = *genp;
        __threadfence();
        if (atomicAdd(&g_bar_count, 1u) == gridDim.x - 1) {
            g_bar_count = 0;
            __threadfence();
            atomicAdd(&g_bar_gen, 1u);
        } else {
            while (*genp == g) { __nanosleep(32); }
        }
        __threadfence();
    }
    __syncthreads();
}

// ---------------- xg = emb @ Wih^T + bih : 128x128 tile, f32x2 ----------------
__global__ __launch_bounds__(256) void k_xg(const float* __restrict__ A,
                                            const float* __restrict__ W,
                                            const float* __restrict__ bias)
{
    __shared__ __align__(16) float As[16][128];
    __shared__ __align__(16) float Bs[16][128];
    int tid = threadIdx.x;
    int tx = tid & 15, ty = tid >> 4;
    int m0 = blockIdx.y * 128, n0 = blockIdx.x * 128;
    ull acc2[8][4];
#pragma unroll
    for (int r = 0; r < 8; ++r)
#pragma unroll
        for (int q = 0; q < 4; ++q) acc2[r][q] = 0ull;

    for (int kb = 0; kb < HH; kb += 16) {
#pragma unroll
        for (int i = 0; i < 2; ++i) {
            int e4 = tid + i * 256;
            int mm = e4 >> 2, k4 = (e4 & 3) << 2;
            float4 v = *(const float4*)&A[(size_t)(m0 + mm) * HH + kb + k4];
            As[k4 + 0][mm] = v.x; As[k4 + 1][mm] = v.y;
            As[k4 + 2][mm] = v.z; As[k4 + 3][mm] = v.w;
        }
#pragma unroll
        for (int i = 0; i < 2; ++i) {
            int e4 = tid + i * 256;
            int nn = e4 >> 2, k4 = (e4 & 3) << 2;
            float4 v = *(const float4*)&W[(size_t)(n0 + nn) * HH + kb + k4];
            Bs[k4 + 0][nn] = v.x; Bs[k4 + 1][nn] = v.y;
            Bs[k4 + 2][nn] = v.z; Bs[k4 + 3][nn] = v.w;
        }
        __syncthreads();
#pragma unroll
        for (int kk = 0; kk < 16; ++kk) {
            float4 a0 = *(const float4*)&As[kk][ty * 8];
            float4 a1 = *(const float4*)&As[kk][ty * 8 + 4];
            ull da[8];
            da[0] = dup2(a0.x); da[1] = dup2(a0.y);
            da[2] = dup2(a0.z); da[3] = dup2(a0.w);
            da[4] = dup2(a1.x); da[5] = dup2(a1.y);
            da[6] = dup2(a1.z); da[7] = dup2(a1.w);
            ull wb[4];
#pragma unroll
            for (int q = 0; q < 4; ++q)
                wb[q] = *(const ull*)&Bs[kk][tx * 8 + 2 * q];
#pragma unroll
            for (int r = 0; r < 8; ++r)
#pragma unroll
                for (int q = 0; q < 4; ++q)
                    acc2[r][q] = ffma2(wb[q], da[r], acc2[r][q]);
        }
        __syncthreads();
    }
#pragma unroll
    for (int r = 0; r < 8; ++r) {
        int m = m0 + ty * 8 + r;
        int n = n0 + tx * 8;
        float2 p0 = unpk2(acc2[r][0]), p1 = unpk2(acc2[r][1]);
        float2 p2 = unpk2(acc2[r][2]), p3 = unpk2(acc2[r][3]);
        float4 o0, o1;
        o0.x = p0.x + bias[n + 0]; o0.y = p0.y + bias[n + 1];
        o0.z = p1.x + bias[n + 2]; o0.w = p1.y + bias[n + 3];
        o1.x = p2.x + bias[n + 4]; o1.y = p2.y + bias[n + 5];
        o1.z = p3.x + bias[n + 6]; o1.w = p3.y + bias[n + 7];
        *(float4*)&g_xg[(size_t)m * (3 * HH) + n] = o0;
        *(float4*)&g_xg[(size_t)m * (3 * HH) + n + 4] = o1;
    }
}

// ---------------- persistent GRU: 148 blocks x 224 thr, f32x2 batch pairs -----
__global__ __launch_bounds__(224) void k_gru(const float* __restrict__ h0,
                                             const float* __restrict__ Whh,
                                             const float* __restrict__ bhh,
                                             float* __restrict__ outHT)
{
    __shared__ __align__(16) float hs[BB][HH];
    int tid = threadIdx.x;
    int lane = tid & 31, wid = tid >> 5;
    int j = blockIdx.x * GW + wid;
    bool valid = (j < HH);
    int c = j & 127, f = j >> 7;

    float4 wr4[8], wz4[8], wn4[8];
    float br = 0.f, bz = 0.f, bn = 0.f;
    if (valid) {
        const float* wr = Whh + (size_t)j * HH;
        const float* wz = Whh + (size_t)(j + HH) * HH;
        const float* wn = Whh + (size_t)(j + 2 * HH) * HH;
#pragma unroll
        for (int i = 0; i < 8; ++i) {
            wr4[i] = *(const float4*)&wr[i * 128 + lane * 4];
            wz4[i] = *(const float4*)&wz[i * 128 + lane * 4];
            wn4[i] = *(const float4*)&wn[i * 128 + lane * 4];
        }
        br = bhh[j]; bz = bhh[j + HH]; bn = bhh[j + 2 * HH];
    } else {
#pragma unroll
        for (int i = 0; i < 8; ++i) {
            wr4[i] = make_float4(0, 0, 0, 0);
            wz4[i] = make_float4(0, 0, 0, 0);
            wn4[i] = make_float4(0, 0, 0, 0);
        }
    }

    {
        int i = blockIdx.x * 224 + tid;
        if (i < BB * HH) g_h[0][i] = h0[i];
    }
    grid_barrier();

    for (int t = 0; t < TT; ++t) {
        const float4* hp = (const float4*)&g_h[t & 1][0];
        float* hw = &g_h[(t + 1) & 1][0];
#pragma unroll
        for (int i = 0; i < 10; ++i) {
            int idx4 = tid + i * 224;
            if (idx4 < 2048) {
                float4 v = hp[idx4];
                *(float4*)&hs[idx4 >> 8][(idx4 & 255) * 4] = v;
            }
        }
        __syncthreads();

        float xr = 0.f, xz = 0.f, xn = 0.f;
        if (valid && lane < 8) {
            const float* xgp = g_xg + (size_t)(lane * TT + t) * (3 * HH);
            xr = xgp[j]; xz = xgp[j + HH]; xn = xgp[j + 2 * HH];
        }

        // packed accumulators: aX[bp] holds batches (2bp, 2bp+1) in (.x, .y)
        ull aR[4], aZ[4], aN[4];
#pragma unroll
        for (int bp = 0; bp < 4; ++bp) { aR[bp] = 0ull; aZ[bp] = 0ull; aN[bp] = 0ull; }

        if (valid) {
#pragma unroll
            for (int i = 0; i < 8; ++i) {
                float4 wr = wr4[i], wz = wz4[i], wn = wn4[i];
                ull dwr0 = dup2(wr.x), dwr1 = dup2(wr.y), dwr2 = dup2(wr.z), dwr3 = dup2(wr.w);
                ull dwz0 = dup2(wz.x), dwz1 = dup2(wz.y), dwz2 = dup2(wz.z), dwz3 = dup2(wz.w);
                ull dwn0 = dup2(wn.x), dwn1 = dup2(wn.y), dwn2 = dup2(wn.z), dwn3 = dup2(wn.w);
                int ko = i * 128 + lane * 4;
#pragma unroll
                for (int bp = 0; bp < 4; ++bp) {
                    float4 h0v = *(const float4*)&hs[2 * bp + 0][ko];
                    float4 h1v = *(const float4*)&hs[2 * bp + 1][ko];
                    ull p0 = pack2(h0v.x, h1v.x);
                    ull p1 = pack2(h0v.y, h1v.y);
                    ull p2 = pack2(h0v.z, h1v.z);
                    ull p3 = pack2(h0v.w, h1v.w);
                    aR[bp] = ffma2(dwr0, p0, aR[bp]);
                    aR[bp] = ffma2(dwr1, p1, aR[bp]);
                    aR[bp] = ffma2(dwr2, p2, aR[bp]);
                    aR[bp] = ffma2(dwr3, p3, aR[bp]);
                    aZ[bp] = ffma2(dwz0, p0, aZ[bp]);
                    aZ[bp] = ffma2(dwz1, p1, aZ[bp]);
                    aZ[bp] = ffma2(dwz2, p2, aZ[bp]);
                    aZ[bp] = ffma2(dwz3, p3, aZ[bp]);
                    aN[bp] = ffma2(dwn0, p0, aN[bp]);
                    aN[bp] = ffma2(dwn1, p1, aN[bp]);
                    aN[bp] = ffma2(dwn2, p2, aN[bp]);
                    aN[bp] = ffma2(dwn3, p3, aN[bp]);
                }
            }
            // packed butterfly reduction (adds in same order as scalar version)
#pragma unroll
            for (int bp = 0; bp < 4; ++bp) {
#pragma unroll
                for (int off = 16; off; off >>= 1) {
                    {
                        ull o = __shfl_xor_sync(0xffffffffu, aR[bp], off);
                        float2 s = unpk2(aR[bp]), v = unpk2(o);
                        aR[bp] = pack2(s.x + v.x, s.y + v.y);
                    }
                    {
                        ull o = __shfl_xor_sync(0xffffffffu, aZ[bp], off);
                        float2 s = unpk2(aZ[bp]), v = unpk2(o);
                        aZ[bp] = pack2(s.x + v.x, s.y + v.y);
                    }
                    {
                        ull o = __shfl_xor_sync(0xffffffffu, aN[bp], off);
                        float2 s = unpk2(aN[bp]), v = unpk2(o);
                        aN[bp] = pack2(s.x + v.x, s.y + v.y);
                    }
                }
            }
            if (lane < 8) {
                int b = lane;
                int bp = b >> 1;
                ull ur = (bp == 0) ? aR[0] : (bp == 1) ? aR[1] : (bp == 2) ? aR[2] : aR[3];
                ull uz = (bp == 0) ? aZ[0] : (bp == 1) ? aZ[1] : (bp == 2) ? aZ[2] : aZ[3];
                ull un = (bp == 0) ? aN[0] : (bp == 1) ? aN[1] : (bp == 2) ? aN[2] : aN[3];
                float2 fr = unpk2(ur), fz = unpk2(uz), fn = unpk2(un);
                float sr = (b & 1) ? fr.y : fr.x;
                float sz = (b & 1) ? fz.y : fz.x;
                float sn = (b & 1) ? fn.y : fn.x;
                float r = 1.f / (1.f + __expf(-(xr + sr + br)));
                float z = 1.f / (1.f + __expf(-(xz + sz + bz)));
                float n = tanhf(xn + r * (sn + bn));
                float hnew = (1.f - z) * n + z * hs[b][j];
                hw[b * HH + j] = hnew;
                g_emb2[((size_t)(b * CC + c) * TT + t) * 8 + f] = hnew;
                if (t == TT - 1) outHT[b * HH + j] = hnew;
            }
        }
        grid_barrier();
    }
}

// ---------------- 1x1 conv over channels + bias + skip, f32x2 ----------------
__global__ __launch_bounds__(256) void k_pconv(float* __restrict__ out,
                                               const float* __restrict__ in,
                                               const float* __restrict__ W,
                                               const float* __restrict__ bias,
                                               const float* __restrict__ skip,
                                               int TF)
{
    __shared__ __align__(16) float Xs[128][64];
    __shared__ __align__(16) float Ws[16][128];
    int tid = threadIdx.x;
    int tx = tid & 15, ty = tid >> 4;
    int b = blockIdx.y;
    int p0 = blockIdx.x * 64;

#pragma unroll
    for (int i = 0; i < 8; ++i) {
        int e4 = tid + i * 256;
        int ch = e4 >> 4, pq = (e4 & 15) << 2;
        *(float4*)&Xs[ch][pq] = *(const float4*)&in[(size_t)(b * CC + ch) * TF + p0 + pq];
    }
    ull acc2[4][4];
#pragma unroll
    for (int p = 0; p < 4; ++p)
#pragma unroll
        for (int q = 0; q < 4; ++q) acc2[p][q] = 0ull;

    for (int kb = 0; kb < CC; kb += 16) {
#pragma unroll
        for (int i = 0; i < 2; ++i) {
            int e4 = tid * 2 + i;
            int oc = e4 >> 2, k4 = (e4 & 3) << 2;
            float4 v = *(const float4*)&W[oc * CC + kb + k4];
            Ws[k4 + 0][oc] = v.x; Ws[k4 + 1][oc] = v.y;
            Ws[k4 + 2][oc] = v.z; Ws[k4 + 3][oc] = v.w;
        }
        __syncthreads();
#pragma unroll
        for (int kk = 0; kk < 16; ++kk) {
            float4 xv = *(const float4*)&Xs[kb + kk][tx * 4];
            ull dx[4];
            dx[0] = dup2(xv.x); dx[1] = dup2(xv.y);
            dx[2] = dup2(xv.z); dx[3] = dup2(xv.w);
            ull wp[4];
#pragma unroll
            for (int p = 0; p < 4; ++p)
                wp[p] = *(const ull*)&Ws[kk][ty * 8 + 2 * p];
#pragma unroll
            for (int p = 0; p < 4; ++p)
#pragma unroll
                for (int q = 0; q < 4; ++q)
                    acc2[p][q] = ffma2(wp[p], dx[q], acc2[p][q]);
        }
        __syncthreads();
    }
#pragma unroll
    for (int p = 0; p < 4; ++p) {
        int oc0 = ty * 8 + 2 * p, oc1 = oc0 + 1;
        float2 u0 = unpk2(acc2[p][0]), u1 = unpk2(acc2[p][1]);
        float2 u2 = unpk2(acc2[p][2]), u3 = unpk2(acc2[p][3]);
        size_t i0 = (size_t)(b * CC + oc0) * TF + p0 + tx * 4;
        size_t i1 = (size_t)(b * CC + oc1) * TF + p0 + tx * 4;
        float bv0 = bias[oc0], bv1 = bias[oc1];
        float4 s0 = *(const float4*)&skip[i0];
        float4 s1 = *(const float4*)&skip[i1];
        float4 o0, o1;
        o0.x = u0.x + bv0 + s0.x; o0.y = u1.x + bv0 + s0.y;
        o0.z = u2.x + bv0 + s0.z; o0.w = u3.x + bv0 + s0.w;
        o1.x = u0.y + bv1 + s1.x; o1.y = u1.y + bv1 + s1.y;
        o1.z = u2.y + bv1 + s1.z; o1.w = u3.y + bv1 + s1.w;
        *(float4*)&out[i0] = o0;
        *(float4*)&out[i1] = o1;
    }
}

// ---------------- weight transpose for convt: (oc,ic,tap) -> [tap][ic][oc] ----
__global__ __launch_bounds__(256) void k_wtT(const float* __restrict__ src)
{
    int i = blockIdx.x * 256 + threadIdx.x;
    if (i < 3 * CC * CC) {
        int oc = i & 127, ic = (i >> 7) & 127, tap = i >> 14;
        g_wtT[i] = src[(oc * CC + ic) * 3 + tap];
    }
}

// ---------------- transposed conv over freq (k=3,s=2) + ReLU, f32x2 ----------
__global__ __launch_bounds__(128) void k_convt(float* __restrict__ out,
                                               const float* __restrict__ in,
                                               const float* __restrict__ bias,
                                               int Fin, int TF)
{
    __shared__ __align__(16) float Xs[128][36];
    __shared__ __align__(16) float Ws[3][16][128];
    int tid = threadIdx.x;
    int tx = tid & 7, ty = tid >> 3;
    int b = blockIdx.y;
    int p0 = blockIdx.x * 32;

#pragma unroll
    for (int i = 0; i < 8; ++i) {
        int e4 = tid + i * 128;
        int ch = e4 >> 3, pq = (e4 & 7) << 2;
        *(float4*)&Xs[ch][pq] = *(const float4*)&in[(size_t)(b * CC + ch) * TF + p0 + pq];
    }
    int p_ = tx * 4;
    bool sh[4];
#pragma unroll
    for (int jj = 0; jj < 4; ++jj) sh[jj] = (((p_ + jj) & (Fin - 1)) != Fin - 1);

    ull ae2[4][4], ao2[4][4];
#pragma unroll
    for (int p = 0; p < 4; ++p)
#pragma unroll
        for (int q = 0; q < 4; ++q) { ae2[p][q] = 0ull; ao2[p][q] = 0ull; }

    for (int kb = 0; kb < CC; kb += 16) {
        __syncthreads();
#pragma unroll
        for (int i = 0; i < 12; ++i) {
            int idx = tid + i * 128;
            int tap = idx / 512, rem = idx & 511;
            int kkk = rem >> 5, oc4 = (rem & 31) << 2;
            *(float4*)&Ws[tap][kkk][oc4] =
                *(const float4*)&g_wtT[(tap * CC + kb + kkk) * CC + oc4];
        }
        __syncthreads();
#pragma unroll
        for (int kk = 0; kk < 16; ++kk) {
            const float* xrow = &Xs[kb + kk][0];
            float4 xv = *(const float4*)&xrow[p_];
            float xnext = xrow[p_ + 4];
            ull dx[4], dxs[4];
            dx[0] = dup2(xv.x); dx[1] = dup2(xv.y);
            dx[2] = dup2(xv.z); dx[3] = dup2(xv.w);
            dxs[0] = dup2(sh[0] ? xv.y : 0.f);
            dxs[1] = dup2(sh[1] ? xv.z : 0.f);
            dxs[2] = dup2(sh[2] ? xv.w : 0.f);
            dxs[3] = dup2(sh[3] ? xnext : 0.f);
            ull w0p[4], w1p[4], w2p[4];
#pragma unroll
            for (int p = 0; p < 4; ++p) {
                w0p[p] = *(const ull*)&Ws[0][kk][ty * 8 + 2 * p];
                w1p[p] = *(const ull*)&Ws[1][kk][ty * 8 + 2 * p];
                w2p[p] = *(const ull*)&Ws[2][kk][ty * 8 + 2 * p];
            }
#pragma unroll
            for (int p = 0; p < 4; ++p)
#pragma unroll
                for (int q = 0; q < 4; ++q) {
                    ae2[p][q] = ffma2(w1p[p], dx[q], ae2[p][q]);
                    ao2[p][q] = ffma2(w0p[p], dx[q], ao2[p][q]);
                    ao2[p][q] = ffma2(w2p[p], dxs[q], ao2[p][q]);
                }
        }
    }
    int TF2 = TF * 2;
#pragma unroll
    for (int p = 0; p < 4; ++p) {
        int oc0 = ty * 8 + 2 * p, oc1 = oc0 + 1;
        float bv0 = bias[oc0], bv1 = bias[oc1];
#pragma unroll
        for (int q = 0; q < 4; ++q) {
            int pp = p0 + p_ + q;
            float2 e = unpk2(ae2[p][q]);
            float2 o = unpk2(ao2[p][q]);
            float2 r0, r1;
            r0.x = fmaxf(e.x + bv0, 0.f); r0.y = fmaxf(o.x + bv0, 0.f);
            r1.x = fmaxf(e.y + bv1, 0.f); r1.y = fmaxf(o.y + bv1, 0.f);
            *(float2*)&out[(size_t)(b * CC + oc0) * TF2 + 2 * pp] = r0;
            *(float2*)&out[(size_t)(b * CC + oc1) * TF2 + 2 * pp] = r1;
        }
    }
}

// ---------------- final: pre = w0p@e0 + b0p + e1x ; m = sigmoid(conv3(pre)) ----
__global__ __launch_bounds__(256) void k_final(const float* __restrict__ e0,
                                               const float* __restrict__ W,
                                               const float* __restrict__ bias,
                                               const float* __restrict__ w0o,
                                               const float* __restrict__ b0o,
                                               float* __restrict__ outm)
{
    __shared__ __align__(16) float Xs[128][64];
    __shared__ __align__(16) float Ws[16][128];
    __shared__ float wo[128][3];
    const int TF = TT * 64;
    int tid = threadIdx.x;
    int tx = tid & 15, ty = tid >> 4;
    int b = blockIdx.y, t = blockIdx.x;
    int p0 = t * 64;

#pragma unroll
    for (int i = 0; i < 8; ++i) {
        int e4 = tid + i * 256;
        int ch = e4 >> 4, pq = (e4 & 15) << 2;
        *(float4*)&Xs[ch][pq] = *(const float4*)&e0[(size_t)(b * CC + ch) * TF + p0 + pq];
    }
    for (int i = tid; i < 384; i += 256) wo[i / 3][i % 3] = w0o[i];

    ull acc2[4][4];
#pragma unroll
    for (int p = 0; p < 4; ++p)
#pragma unroll
        for (int q = 0; q < 4; ++q) acc2[p][q] = 0ull;

    for (int kb = 0; kb < CC; kb += 16) {
#pragma unroll
        for (int i = 0; i < 2; ++i) {
            int e4 = tid * 2 + i;
            int oc = e4 >> 2, k4 = (e4 & 3) << 2;
            float4 v = *(const float4*)&W[oc * CC + kb + k4];
            Ws[k4 + 0][oc] = v.x; Ws[k4 + 1][oc] = v.y;
            Ws[k4 + 2][oc] = v.z; Ws[k4 + 3][oc] = v.w;
        }
        __syncthreads();
#pragma unroll
        for (int kk = 0; kk < 16; ++kk) {
            float4 xv = *(const float4*)&Xs[kb + kk][tx * 4];
            ull dx[4];
            dx[0] = dup2(xv.x); dx[1] = dup2(xv.y);
            dx[2] = dup2(xv.z); dx[3] = dup2(xv.w);
            ull wp[4];
#pragma unroll
            for (int p = 0; p < 4; ++p)
                wp[p] = *(const ull*)&Ws[kk][ty * 8 + 2 * p];
#pragma unroll
            for (int p = 0; p < 4; ++p)
#pragma unroll
                for (int q = 0; q < 4; ++q)
                    acc2[p][q] = ffma2(wp[p], dx[q], acc2[p][q]);
        }
        __syncthreads();
    }
#pragma unroll
    for (int p = 0; p < 4; ++p) {
        int oc0 = ty * 8 + 2 * p, oc1 = oc0 + 1;
        float bv0 = bias[oc0], bv1 = bias[oc1];
        float2 u0 = unpk2(acc2[p][0]), u1 = unpk2(acc2[p][1]);
        float2 u2 = unpk2(acc2[p][2]), u3 = unpk2(acc2[p][3]);
        int pq = tx * 4;
        Xs[oc0][pq + 0] = u0.x + bv0 + g_e1x[(size_t)(b * CC + oc0) * TF + p0 + pq + 0];
        Xs[oc0][pq + 1] = u1.x + bv0 + g_e1x[(size_t)(b * CC + oc0) * TF + p0 + pq + 1];
        Xs[oc0][pq + 2] = u2.x + bv0 + g_e1x[(size_t)(b * CC + oc0) * TF + p0 + pq + 2];
        Xs[oc0][pq + 3] = u3.x + bv0 + g_e1x[(size_t)(b * CC + oc0) * TF + p0 + pq + 3];
        Xs[oc1][pq + 0] = u0.y + bv1 + g_e1x[(size_t)(b * CC + oc1) * TF + p0 + pq + 0];
        Xs[oc1][pq + 1] = u1.y + bv1 + g_e1x[(size_t)(b * CC + oc1) * TF + p0 + pq + 1];
        Xs[oc1][pq + 2] = u2.y + bv1 + g_e1x[(size_t)(b * CC + oc1) * TF + p0 + pq + 2];
        Xs[oc1][pq + 3] = u3.y + bv1 + g_e1x[(size_t)(b * CC + oc1) * TF + p0 + pq + 3];
    }
    __syncthreads();
    int f = tid >> 2, q = tid & 3;
    float s = 0.f;
#pragma unroll 4
    for (int i = 0; i < 32; ++i) {
        int ch = q * 32 + i;
        float x0 = Xs[ch][f];
        float xm = (f > 0) ? Xs[ch][f - 1] : 0.f;
        float xp = (f < 63) ? Xs[ch][f + 1] : 0.f;
        s = fmaf(wo[ch][0], xm, s);
        s = fmaf(wo[ch][1], x0, s);
        s = fmaf(wo[ch][2], xp, s);
    }
    s += __shfl_down_sync(0xffffffffu, s, 1);
    s += __shfl_down_sync(0xffffffffu, s, 2);
    if (q == 0) outm[((size_t)b * TT + t) * 64 + f] = 1.f / (1.f + __expf(-(s + b0o[0])));
}

// ---------------------------------- launch ----------------------------------
extern "C" void kernel_launch(void* const* d_in, const int* in_sizes, int n_in,
                              void* d_out, int out_size)
{
    const float* emb   = (const float*)d_in[0];
    const float* e3    = (const float*)d_in[1];
    const float* e2    = (const float*)d_in[2];
    const float* e1    = (const float*)d_in[3];
    const float* e0    = (const float*)d_in[4];
    const float* h_erb = (const float*)d_in[5];
    const float* Wih   = (const float*)d_in[6];
    const float* Whh   = (const float*)d_in[7];
    const float* bih   = (const float*)d_in[8];
    const float* bhh   = (const float*)d_in[9];
    const float* w3p   = (const float*)d_in[10];
    const float* b3p   = (const float*)d_in[11];
    const float* w2p   = (const float*)d_in[12];
    const float* b2p   = (const float*)d_in[13];
    const float* w1p   = (const float*)d_in[14];
    const float* b1p   = (const float*)d_in[15];
    const float* w0p   = (const float*)d_in[16];
    const float* b0p   = (const float*)d_in[17];
    const float* wt3   = (const float*)d_in[18];
    const float* bt3   = (const float*)d_in[19];
    const float* wt2   = (const float*)d_in[20];
    const float* bt2   = (const float*)d_in[21];
    const float* wt1   = (const float*)d_in[22];
    const float* bt1   = (const float*)d_in[23];
    const float* w0o   = (const float*)d_in[24];
    const float* b0o   = (const float*)d_in[25];
    float* out = (float*)d_out;

    float* gx3;  cudaGetSymbolAddress((void**)&gx3,  g_x3);
    float* ge3x; cudaGetSymbolAddress((void**)&ge3x, g_e3x);
    float* gx2;  cudaGetSymbolAddress((void**)&gx2,  g_x2);
    float* ge2x; cudaGetSymbolAddress((void**)&ge2x, g_e2x);
    float* gx1;  cudaGetSymbolAddress((void**)&gx1,  g_x1);
    float* ge1x; cudaGetSymbolAddress((void**)&ge1x, g_e1x);
    float* gemb2;cudaGetSymbolAddress((void**)&gemb2,g_emb2);

    k_xg<<<dim3(24, 32), 256>>>(emb, Wih, bih);
    k_gru<<<GBLK, 224>>>(h_erb, Whh, bhh, out + BB * TT * 64);

    k_pconv<<<dim3(64, 8),  256>>>(gx3, e3, w3p, b3p, gemb2, TT * 8);
    k_wtT<<<192, 256>>>(wt3);
    k_convt<<<dim3(128, 8), 128>>>(ge3x, gx3, bt3, 8, TT * 8);

    k_pconv<<<dim3(128, 8), 256>>>(gx2, e2, w2p, b2p, ge3x, TT * 16);
    k_wtT<<<192, 256>>>(wt2);
    k_convt<<<dim3(256, 8), 128>>>(ge2x, gx2, bt2, 16, TT * 16);

    k_pconv<<<dim3(256, 8), 256>>>(gx1, e1, w1p, b1p, ge2x, TT * 32);
    k_wtT<<<192, 256>>>(wt1);
    k_convt<<<dim3(512, 8), 128>>>(ge1x, gx1, bt1, 32, TT * 32);

    k_final<<<dim3(512, 8), 256>>>(e0, w0p, b0p, w0o, b0o, out);
}

// round 7
// speedup vs baseline: 1.0501x; 1.0501x over previous
#include <cuda_runtime.h>

#define BB 8
#define TT 512
#define CC 128
#define HH 1024
#define GBLK 148
#define GW 7

typedef unsigned long long ull;

// ---------------- f32x2 helpers (decoder kernels) ----------------
__device__ __forceinline__ ull dup2(float x)
{
    ull r;
    asm("mov.b64 %0, {%1, %1};" : "=l"(r) : "f"(x));
    return r;
}
__device__ __forceinline__ ull ffma2(ull a, ull b, ull c)
{
    ull d;
    asm("fma.rn.f32x2 %0, %1, %2, %3;" : "=l"(d) : "l"(a), "l"(b), "l"(c));
    return d;
}
__device__ __forceinline__ float2 unpk2(ull v)
{
    float2 f;
    asm("mov.b64 {%0, %1}, %2;" : "=f"(f.x), "=f"(f.y) : "l"(v));
    return f;
}

// ---------------- static scratch ----------------
__device__ float g_xg[BB * TT * 3 * HH];
__device__ float g_h[2][BB * HH];
__device__ float g_emb2[BB * CC * TT * 8];
__device__ float g_x3[BB * CC * TT * 8];
__device__ float g_e3x[BB * CC * TT * 16];
__device__ float g_x2[BB * CC * TT * 16];
__device__ float g_e2x[BB * CC * TT * 32];
__device__ float g_x1[BB * CC * TT * 32];
__device__ float g_e1x[BB * CC * TT * 64];
__device__ float g_wtT3[3 * CC * CC];
__device__ float g_wtT2[3 * CC * CC];
__device__ float g_wtT1[3 * CC * CC];
__device__ unsigned g_bar_count;
__device__ unsigned g_bar_gen;

// ---------------- barrier state reset (per launch, keeps graph replays valid) --
__global__ void k_reset()
{
    if (threadIdx.x == 0) { g_bar_count = 0; g_bar_gen = 0; }
}

// ---------------- acquire/release grid barrier (all blocks resident) ----------
// my_gen: per-thread generation counter, incremented by caller before each use.
__device__ __forceinline__ void grid_barrier(unsigned my_gen)
{
    __syncthreads();
    if (threadIdx.x == 0) {
        unsigned arr;
        asm volatile("atom.add.release.gpu.u32 %0, [%1], 1;"
                     : "=r"(arr) : "l"(&g_bar_count) : "memory");
        if (arr == GBLK - 1) {
            g_bar_count = 0;
            asm volatile("st.release.gpu.u32 [%0], %1;"
                         :: "l"(&g_bar_gen), "r"(my_gen) : "memory");
        } else {
            unsigned cur;
            do {
                asm volatile("ld.acquire.gpu.u32 %0, [%1];"
                             : "=r"(cur) : "l"(&g_bar_gen) : "memory");
            } while ((int)(cur - my_gen) < 0);
        }
    }
    __syncthreads();
}

// ---------------- xg = emb @ Wih^T + bih : 128x128 tile, f32x2 ----------------
__global__ __launch_bounds__(256) void k_xg(const float* __restrict__ A,
                                            const float* __restrict__ W,
                                            const float* __restrict__ bias)
{
    __shared__ __align__(16) float As[16][128];
    __shared__ __align__(16) float Bs[16][128];
    int tid = threadIdx.x;
    int tx = tid & 15, ty = tid >> 4;
    int m0 = blockIdx.y * 128, n0 = blockIdx.x * 128;
    ull acc2[8][4];
#pragma unroll
    for (int r = 0; r < 8; ++r)
#pragma unroll
        for (int q = 0; q < 4; ++q) acc2[r][q] = 0ull;

    for (int kb = 0; kb < HH; kb += 16) {
#pragma unroll
        for (int i = 0; i < 2; ++i) {
            int e4 = tid + i * 256;
            int mm = e4 >> 2, k4 = (e4 & 3) << 2;
            float4 v = *(const float4*)&A[(size_t)(m0 + mm) * HH + kb + k4];
            As[k4 + 0][mm] = v.x; As[k4 + 1][mm] = v.y;
            As[k4 + 2][mm] = v.z; As[k4 + 3][mm] = v.w;
        }
#pragma unroll
        for (int i = 0; i < 2; ++i) {
            int e4 = tid + i * 256;
            int nn = e4 >> 2, k4 = (e4 & 3) << 2;
            float4 v = *(const float4*)&W[(size_t)(n0 + nn) * HH + kb + k4];
            Bs[k4 + 0][nn] = v.x; Bs[k4 + 1][nn] = v.y;
            Bs[k4 + 2][nn] = v.z; Bs[k4 + 3][nn] = v.w;
        }
        __syncthreads();
#pragma unroll
        for (int kk = 0; kk < 16; ++kk) {
            float4 a0 = *(const float4*)&As[kk][ty * 8];
            float4 a1 = *(const float4*)&As[kk][ty * 8 + 4];
            ull da[8];
            da[0] = dup2(a0.x); da[1] = dup2(a0.y);
            da[2] = dup2(a0.z); da[3] = dup2(a0.w);
            da[4] = dup2(a1.x); da[5] = dup2(a1.y);
            da[6] = dup2(a1.z); da[7] = dup2(a1.w);
            ull wb[4];
#pragma unroll
            for (int q = 0; q < 4; ++q)
                wb[q] = *(const ull*)&Bs[kk][tx * 8 + 2 * q];
#pragma unroll
            for (int r = 0; r < 8; ++r)
#pragma unroll
                for (int q = 0; q < 4; ++q)
                    acc2[r][q] = ffma2(wb[q], da[r], acc2[r][q]);
        }
        __syncthreads();
    }
#pragma unroll
    for (int r = 0; r < 8; ++r) {
        int m = m0 + ty * 8 + r;
        int n = n0 + tx * 8;
        float2 p0 = unpk2(acc2[r][0]), p1 = unpk2(acc2[r][1]);
        float2 p2 = unpk2(acc2[r][2]), p3 = unpk2(acc2[r][3]);
        float4 o0, o1;
        o0.x = p0.x + bias[n + 0]; o0.y = p0.y + bias[n + 1];
        o0.z = p1.x + bias[n + 2]; o0.w = p1.y + bias[n + 3];
        o1.x = p2.x + bias[n + 4]; o1.y = p2.y + bias[n + 5];
        o1.z = p3.x + bias[n + 6]; o1.w = p3.y + bias[n + 7];
        *(float4*)&g_xg[(size_t)m * (3 * HH) + n] = o0;
        *(float4*)&g_xg[(size_t)m * (3 * HH) + n + 4] = o1;
    }
}

// ---------------- persistent GRU: 148 blocks x 224 thr, scalar reg Whh --------
__global__ __launch_bounds__(224) void k_gru(const float* __restrict__ h0,
                                             const float* __restrict__ Whh,
                                             const float* __restrict__ bhh,
                                             float* __restrict__ outHT)
{
    __shared__ __align__(16) float hs[BB][HH];
    int tid = threadIdx.x;
    int lane = tid & 31, wid = tid >> 5;
    int j = blockIdx.x * GW + wid;
    bool valid = (j < HH);
    int c = j & 127, f = j >> 7;

    float4 wr4[8], wz4[8], wn4[8];
    float br = 0.f, bz = 0.f, bn = 0.f;
    if (valid) {
        const float* wr = Whh + (size_t)j * HH;
        const float* wz = Whh + (size_t)(j + HH) * HH;
        const float* wn = Whh + (size_t)(j + 2 * HH) * HH;
#pragma unroll
        for (int i = 0; i < 8; ++i) {
            wr4[i] = *(const float4*)&wr[i * 128 + lane * 4];
            wz4[i] = *(const float4*)&wz[i * 128 + lane * 4];
            wn4[i] = *(const float4*)&wn[i * 128 + lane * 4];
        }
        br = bhh[j]; bz = bhh[j + HH]; bn = bhh[j + 2 * HH];
    } else {
#pragma unroll
        for (int i = 0; i < 8; ++i) {
            wr4[i] = make_float4(0, 0, 0, 0);
            wz4[i] = make_float4(0, 0, 0, 0);
            wn4[i] = make_float4(0, 0, 0, 0);
        }
    }

    unsigned my_gen = 0;
    {
        int i = blockIdx.x * 224 + tid;
        if (i < BB * HH) g_h[0][i] = h0[i];
    }
    ++my_gen;
    grid_barrier(my_gen);

    for (int t = 0; t < TT; ++t) {
        const float4* hp = (const float4*)&g_h[t & 1][0];
        float* hw = &g_h[(t + 1) & 1][0];
#pragma unroll
        for (int i = 0; i < 10; ++i) {
            int idx4 = tid + i * 224;
            if (idx4 < 2048) {
                float4 v = hp[idx4];
                *(float4*)&hs[idx4 >> 8][(idx4 & 255) * 4] = v;
            }
        }
        __syncthreads();

        float xr = 0.f, xz = 0.f, xn = 0.f;
        if (valid && lane < 8) {
            const float* xgp = g_xg + (size_t)(lane * TT + t) * (3 * HH);
            xr = xgp[j]; xz = xgp[j + HH]; xn = xgp[j + 2 * HH];
        }

        float accR[8], accZ[8], accN[8];
#pragma unroll
        for (int b = 0; b < 8; ++b) { accR[b] = 0.f; accZ[b] = 0.f; accN[b] = 0.f; }

        if (valid) {
#pragma unroll
            for (int i = 0; i < 8; ++i) {
                float4 a = wr4[i], b4 = wz4[i], c4 = wn4[i];
#pragma unroll
                for (int b = 0; b < 8; ++b) {
                    float4 h4 = *(const float4*)&hs[b][i * 128 + lane * 4];
                    accR[b] = fmaf(a.x, h4.x, accR[b]);
                    accR[b] = fmaf(a.y, h4.y, accR[b]);
                    accR[b] = fmaf(a.z, h4.z, accR[b]);
                    accR[b] = fmaf(a.w, h4.w, accR[b]);
                    accZ[b] = fmaf(b4.x, h4.x, accZ[b]);
                    accZ[b] = fmaf(b4.y, h4.y, accZ[b]);
                    accZ[b] = fmaf(b4.z, h4.z, accZ[b]);
                    accZ[b] = fmaf(b4.w, h4.w, accZ[b]);
                    accN[b] = fmaf(c4.x, h4.x, accN[b]);
                    accN[b] = fmaf(c4.y, h4.y, accN[b]);
                    accN[b] = fmaf(c4.z, h4.z, accN[b]);
                    accN[b] = fmaf(c4.w, h4.w, accN[b]);
                }
            }
#pragma unroll
            for (int b = 0; b < 8; ++b)
#pragma unroll
                for (int off = 16; off; off >>= 1) {
                    accR[b] += __shfl_xor_sync(0xffffffffu, accR[b], off);
                    accZ[b] += __shfl_xor_sync(0xffffffffu, accZ[b], off);
                    accN[b] += __shfl_xor_sync(0xffffffffu, accN[b], off);
                }
            if (lane < 8) {
                int b = lane;
                float r = 1.f / (1.f + __expf(-(xr + accR[b] + br)));
                float z = 1.f / (1.f + __expf(-(xz + accZ[b] + bz)));
                float n = tanhf(xn + r * (accN[b] + bn));
                float hnew = (1.f - z) * n + z * hs[b][j];
                hw[b * HH + j] = hnew;
                g_emb2[((size_t)(b * CC + c) * TT + t) * 8 + f] = hnew;
                if (t == TT - 1) outHT[b * HH + j] = hnew;
            }
        }
        ++my_gen;
        grid_barrier(my_gen);
    }
}

// ---------------- 1x1 conv over channels + bias + skip, f32x2 ----------------
__global__ __launch_bounds__(256) void k_pconv(float* __restrict__ out,
                                               const float* __restrict__ in,
                                               const float* __restrict__ W,
                                               const float* __restrict__ bias,
                                               const float* __restrict__ skip,
                                               int TF)
{
    __shared__ __align__(16) float Xs[128][64];
    __shared__ __align__(16) float Ws[16][128];
    int tid = threadIdx.x;
    int tx = tid & 15, ty = tid >> 4;
    int b = blockIdx.y;
    int p0 = blockIdx.x * 64;

#pragma unroll
    for (int i = 0; i < 8; ++i) {
        int e4 = tid + i * 256;
        int ch = e4 >> 4, pq = (e4 & 15) << 2;
        *(float4*)&Xs[ch][pq] = *(const float4*)&in[(size_t)(b * CC + ch) * TF + p0 + pq];
    }
    ull acc2[4][4];
#pragma unroll
    for (int p = 0; p < 4; ++p)
#pragma unroll
        for (int q = 0; q < 4; ++q) acc2[p][q] = 0ull;

    for (int kb = 0; kb < CC; kb += 16) {
#pragma unroll
        for (int i = 0; i < 2; ++i) {
            int e4 = tid * 2 + i;
            int oc = e4 >> 2, k4 = (e4 & 3) << 2;
            float4 v = *(const float4*)&W[oc * CC + kb + k4];
            Ws[k4 + 0][oc] = v.x; Ws[k4 + 1][oc] = v.y;
            Ws[k4 + 2][oc] = v.z; Ws[k4 + 3][oc] = v.w;
        }
        __syncthreads();
#pragma unroll
        for (int kk = 0; kk < 16; ++kk) {
            float4 xv = *(const float4*)&Xs[kb + kk][tx * 4];
            ull dx[4];
            dx[0] = dup2(xv.x); dx[1] = dup2(xv.y);
            dx[2] = dup2(xv.z); dx[3] = dup2(xv.w);
            ull wp[4];
#pragma unroll
            for (int p = 0; p < 4; ++p)
                wp[p] = *(const ull*)&Ws[kk][ty * 8 + 2 * p];
#pragma unroll
            for (int p = 0; p < 4; ++p)
#pragma unroll
                for (int q = 0; q < 4; ++q)
                    acc2[p][q] = ffma2(wp[p], dx[q], acc2[p][q]);
        }
        __syncthreads();
    }
#pragma unroll
    for (int p = 0; p < 4; ++p) {
        int oc0 = ty * 8 + 2 * p, oc1 = oc0 + 1;
        float2 u0 = unpk2(acc2[p][0]), u1 = unpk2(acc2[p][1]);
        float2 u2 = unpk2(acc2[p][2]), u3 = unpk2(acc2[p][3]);
        size_t i0 = (size_t)(b * CC + oc0) * TF + p0 + tx * 4;
        size_t i1 = (size_t)(b * CC + oc1) * TF + p0 + tx * 4;
        float bv0 = bias[oc0], bv1 = bias[oc1];
        float4 s0 = *(const float4*)&skip[i0];
        float4 s1 = *(const float4*)&skip[i1];
        float4 o0, o1;
        o0.x = u0.x + bv0 + s0.x; o0.y = u1.x + bv0 + s0.y;
        o0.z = u2.x + bv0 + s0.z; o0.w = u3.x + bv0 + s0.w;
        o1.x = u0.y + bv1 + s1.x; o1.y = u1.y + bv1 + s1.y;
        o1.z = u2.y + bv1 + s1.z; o1.w = u3.y + bv1 + s1.w;
        *(float4*)&out[i0] = o0;
        *(float4*)&out[i1] = o1;
    }
}

// ---------------- weight transpose for convt: (oc,ic,tap) -> [tap][ic][oc] ----
__global__ __launch_bounds__(256) void k_wtT(const float* __restrict__ src,
                                             float* __restrict__ dst)
{
    int i = blockIdx.x * 256 + threadIdx.x;
    if (i < 3 * CC * CC) {
        int oc = i & 127, ic = (i >> 7) & 127, tap = i >> 14;
        dst[i] = src[(oc * CC + ic) * 3 + tap];
    }
}

// ---------------- transposed conv over freq (k=3,s=2) + ReLU, f32x2 ----------
__global__ __launch_bounds__(128) void k_convt(float* __restrict__ out,
                                               const float* __restrict__ in,
                                               const float* __restrict__ wT,
                                               const float* __restrict__ bias,
                                               int Fin, int TF)
{
    __shared__ __align__(16) float Xs[128][36];
    __shared__ __align__(16) float Ws[3][16][128];
    int tid = threadIdx.x;
    int tx = tid & 7, ty = tid >> 3;
    int b = blockIdx.y;
    int p0 = blockIdx.x * 32;

#pragma unroll
    for (int i = 0; i < 8; ++i) {
        int e4 = tid + i * 128;
        int ch = e4 >> 3, pq = (e4 & 7) << 2;
        *(float4*)&Xs[ch][pq] = *(const float4*)&in[(size_t)(b * CC + ch) * TF + p0 + pq];
    }
    int p_ = tx * 4;
    bool sh[4];
#pragma unroll
    for (int jj = 0; jj < 4; ++jj) sh[jj] = (((p_ + jj) & (Fin - 1)) != Fin - 1);

    ull ae2[4][4], ao2[4][4];
#pragma unroll
    for (int p = 0; p < 4; ++p)
#pragma unroll
        for (int q = 0; q < 4; ++q) { ae2[p][q] = 0ull; ao2[p][q] = 0ull; }

    for (int kb = 0; kb < CC; kb += 16) {
        __syncthreads();
#pragma unroll
        for (int i = 0; i < 12; ++i) {
            int idx = tid + i * 128;
            int tap = idx / 512, rem = idx & 511;
            int kkk = rem >> 5, oc4 = (rem & 31) << 2;
            *(float4*)&Ws[tap][kkk][oc4] =
                *(const float4*)&wT[(tap * CC + kb + kkk) * CC + oc4];
        }
        __syncthreads();
#pragma unroll
        for (int kk = 0; kk < 16; ++kk) {
            const float* xrow = &Xs[kb + kk][0];
            float4 xv = *(const float4*)&xrow[p_];
            float xnext = xrow[p_ + 4];
            ull dx[4], dxs[4];
            dx[0] = dup2(xv.x); dx[1] = dup2(xv.y);
            dx[2] = dup2(xv.z); dx[3] = dup2(xv.w);
            dxs[0] = dup2(sh[0] ? xv.y : 0.f);
            dxs[1] = dup2(sh[1] ? xv.z : 0.f);
            dxs[2] = dup2(sh[2] ? xv.w : 0.f);
            dxs[3] = dup2(sh[3] ? xnext : 0.f);
            ull w0p[4], w1p[4], w2p[4];
#pragma unroll
            for (int p = 0; p < 4; ++p) {
                w0p[p] = *(const ull*)&Ws[0][kk][ty * 8 + 2 * p];
                w1p[p] = *(const ull*)&Ws[1][kk][ty * 8 + 2 * p];
                w2p[p] = *(const ull*)&Ws[2][kk][ty * 8 + 2 * p];
            }
#pragma unroll
            for (int p = 0; p < 4; ++p)
#pragma unroll
                for (int q = 0; q < 4; ++q) {
                    ae2[p][q] = ffma2(w1p[p], dx[q], ae2[p][q]);
                    ao2[p][q] = ffma2(w0p[p], dx[q], ao2[p][q]);
                    ao2[p][q] = ffma2(w2p[p], dxs[q], ao2[p][q]);
                }
        }
    }
    int TF2 = TF * 2;
#pragma unroll
    for (int p = 0; p < 4; ++p) {
        int oc0 = ty * 8 + 2 * p, oc1 = oc0 + 1;
        float bv0 = bias[oc0], bv1 = bias[oc1];
#pragma unroll
        for (int q = 0; q < 4; ++q) {
            int pp = p0 + p_ + q;
            float2 e = unpk2(ae2[p][q]);
            float2 o = unpk2(ao2[p][q]);
            float2 r0, r1;
            r0.x = fmaxf(e.x + bv0, 0.f); r0.y = fmaxf(o.x + bv0, 0.f);
            r1.x = fmaxf(e.y + bv1, 0.f); r1.y = fmaxf(o.y + bv1, 0.f);
            *(float2*)&out[(size_t)(b * CC + oc0) * TF2 + 2 * pp] = r0;
            *(float2*)&out[(size_t)(b * CC + oc1) * TF2 + 2 * pp] = r1;
        }
    }
}

// ---------------- final: pre = w0p@e0 + b0p + e1x ; m = sigmoid(conv3(pre)) ----
__global__ __launch_bounds__(256) void k_final(const float* __restrict__ e0,
                                               const float* __restrict__ W,
                                               const float* __restrict__ bias,
                                               const float* __restrict__ w0o,
                                               const float* __restrict__ b0o,
                                               float* __restrict__ outm)
{
    __shared__ __align__(16) float Xs[128][64];
    __shared__ __align__(16) float Ws[16][128];
    __shared__ float wo[128][3];
    const int TF = TT * 64;
    int tid = threadIdx.x;
    int tx = tid & 15, ty = tid >> 4;
    int b = blockIdx.y, t = blockIdx.x;
    int p0 = t * 64;

#pragma unroll
    for (int i = 0; i < 8; ++i) {
        int e4 = tid + i * 256;
        int ch = e4 >> 4, pq = (e4 & 15) << 2;
        *(float4*)&Xs[ch][pq] = *(const float4*)&e0[(size_t)(b * CC + ch) * TF + p0 + pq];
    }
    for (int i = tid; i < 384; i += 256) wo[i / 3][i % 3] = w0o[i];

    ull acc2[4][4];
#pragma unroll
    for (int p = 0; p < 4; ++p)
#pragma unroll
        for (int q = 0; q < 4; ++q) acc2[p][q] = 0ull;

    for (int kb = 0; kb < CC; kb += 16) {
#pragma unroll
        for (int i = 0; i < 2; ++i) {
            int e4 = tid * 2 + i;
            int oc = e4 >> 2, k4 = (e4 & 3) << 2;
            float4 v = *(const float4*)&W[oc * CC + kb + k4];
            Ws[k4 + 0][oc] = v.x; Ws[k4 + 1][oc] = v.y;
            Ws[k4 + 2][oc] = v.z; Ws[k4 + 3][oc] = v.w;
        }
        __syncthreads();
#pragma unroll
        for (int kk = 0; kk < 16; ++kk) {
            float4 xv = *(const float4*)&Xs[kb + kk][tx * 4];
            ull dx[4];
            dx[0] = dup2(xv.x); dx[1] = dup2(xv.y);
            dx[2] = dup2(xv.z); dx[3] = dup2(xv.w);
            ull wp[4];
#pragma unroll
            for (int p = 0; p < 4; ++p)
                wp[p] = *(const ull*)&Ws[kk][ty * 8 + 2 * p];
#pragma unroll
            for (int p = 0; p < 4; ++p)
#pragma unroll
                for (int q = 0; q < 4; ++q)
                    acc2[p][q] = ffma2(wp[p], dx[q], acc2[p][q]);
        }
        __syncthreads();
    }
#pragma unroll
    for (int p = 0; p < 4; ++p) {
        int oc0 = ty * 8 + 2 * p, oc1 = oc0 + 1;
        float bv0 = bias[oc0], bv1 = bias[oc1];
        float2 u0 = unpk2(acc2[p][0]), u1 = unpk2(acc2[p][1]);
        float2 u2 = unpk2(acc2[p][2]), u3 = unpk2(acc2[p][3]);
        int pq = tx * 4;
        Xs[oc0][pq + 0] = u0.x + bv0 + g_e1x[(size_t)(b * CC + oc0) * TF + p0 + pq + 0];
        Xs[oc0][pq + 1] = u1.x + bv0 + g_e1x[(size_t)(b * CC + oc0) * TF + p0 + pq + 1];
        Xs[oc0][pq + 2] = u2.x + bv0 + g_e1x[(size_t)(b * CC + oc0) * TF + p0 + pq + 2];
        Xs[oc0][pq + 3] = u3.x + bv0 + g_e1x[(size_t)(b * CC + oc0) * TF + p0 + pq + 3];
        Xs[oc1][pq + 0] = u0.y + bv1 + g_e1x[(size_t)(b * CC + oc1) * TF + p0 + pq + 0];
        Xs[oc1][pq + 1] = u1.y + bv1 + g_e1x[(size_t)(b * CC + oc1) * TF + p0 + pq + 1];
        Xs[oc1][pq + 2] = u2.y + bv1 + g_e1x[(size_t)(b * CC + oc1) * TF + p0 + pq + 2];
        Xs[oc1][pq + 3] = u3.y + bv1 + g_e1x[(size_t)(b * CC + oc1) * TF + p0 + pq + 3];
    }
    __syncthreads();
    int f = tid >> 2, q = tid & 3;
    float s = 0.f;
#pragma unroll 4
    for (int i = 0; i < 32; ++i) {
        int ch = q * 32 + i;
        float x0 = Xs[ch][f];
        float xm = (f > 0) ? Xs[ch][f - 1] : 0.f;
        float xp = (f < 63) ? Xs[ch][f + 1] : 0.f;
        s = fmaf(wo[ch][0], xm, s);
        s = fmaf(wo[ch][1], x0, s);
        s = fmaf(wo[ch][2], xp, s);
    }
    s += __shfl_down_sync(0xffffffffu, s, 1);
    s += __shfl_down_sync(0xffffffffu, s, 2);
    if (q == 0) outm[((size_t)b * TT + t) * 64 + f] = 1.f / (1.f + __expf(-(s + b0o[0])));
}

// ---------------------------------- launch ----------------------------------
extern "C" void kernel_launch(void* const* d_in, const int* in_sizes, int n_in,
                              void* d_out, int out_size)
{
    const float* emb   = (const float*)d_in[0];
    const float* e3    = (const float*)d_in[1];
    const float* e2    = (const float*)d_in[2];
    const float* e1    = (const float*)d_in[3];
    const float* e0    = (const float*)d_in[4];
    const float* h_erb = (const float*)d_in[5];
    const float* Wih   = (const float*)d_in[6];
    const float* Whh   = (const float*)d_in[7];
    const float* bih   = (const float*)d_in[8];
    const float* bhh   = (const float*)d_in[9];
    const float* w3p   = (const float*)d_in[10];
    const float* b3p   = (const float*)d_in[11];
    const float* w2p   = (const float*)d_in[12];
    const float* b2p   = (const float*)d_in[13];
    const float* w1p   = (const float*)d_in[14];
    const float* b1p   = (const float*)d_in[15];
    const float* w0p   = (const float*)d_in[16];
    const float* b0p   = (const float*)d_in[17];
    const float* wt3   = (const float*)d_in[18];
    const float* bt3   = (const float*)d_in[19];
    const float* wt2   = (const float*)d_in[20];
    const float* bt2   = (const float*)d_in[21];
    const float* wt1   = (const float*)d_in[22];
    const float* bt1   = (const float*)d_in[23];
    const float* w0o   = (const float*)d_in[24];
    const float* b0o   = (const float*)d_in[25];
    float* out = (float*)d_out;

    float* gx3;  cudaGetSymbolAddress((void**)&gx3,  g_x3);
    float* ge3x; cudaGetSymbolAddress((void**)&ge3x, g_e3x);
    float* gx2;  cudaGetSymbolAddress((void**)&gx2,  g_x2);
    float* ge2x; cudaGetSymbolAddress((void**)&ge2x, g_e2x);
    float* gx1;  cudaGetSymbolAddress((void**)&gx1,  g_x1);
    float* ge1x; cudaGetSymbolAddress((void**)&ge1x, g_e1x);
    float* gemb2;cudaGetSymbolAddress((void**)&gemb2,g_emb2);
    float* gw3;  cudaGetSymbolAddress((void**)&gw3,  g_wtT3);
    float* gw2;  cudaGetSymbolAddress((void**)&gw2,  g_wtT2);
    float* gw1;  cudaGetSymbolAddress((void**)&gw1,  g_wtT1);

    // launch order chosen so ncu (-s 5 -c 1) profiles k_gru (index 5)
    k_wtT<<<192, 256>>>(wt3, gw3);            // 0
    k_wtT<<<192, 256>>>(wt2, gw2);            // 1
    k_wtT<<<192, 256>>>(wt1, gw1);            // 2
    k_xg<<<dim3(24, 32), 256>>>(emb, Wih, bih); // 3
    k_reset<<<1, 32>>>();                     // 4
    k_gru<<<GBLK, 224>>>(h_erb, Whh, bhh, out + BB * TT * 64); // 5

    k_pconv<<<dim3(64, 8),  256>>>(gx3, e3, w3p, b3p, gemb2, TT * 8);
    k_convt<<<dim3(128, 8), 128>>>(ge3x, gx3, gw3, bt3, 8, TT * 8);

    k_pconv<<<dim3(128, 8), 256>>>(gx2, e2, w2p, b2p, ge3x, TT * 16);
    k_convt<<<dim3(256, 8), 128>>>(ge2x, gx2, gw2, bt2, 16, TT * 16);

    k_pconv<<<dim3(256, 8), 256>>>(gx1, e1, w1p, b1p, ge2x, TT * 32);
    k_convt<<<dim3(512, 8), 128>>>(ge1x, gx1, gw1, bt1, 32, TT * 32);

    k_final<<<dim3(512, 8), 256>>>(e0, w0p, b0p, w0o, b0o, out);
}

// round 9
// speedup vs baseline: 1.1532x; 1.0982x over previous
#include <cuda_runtime.h>
#include <cuda_bf16.h>

#define BB 8
#define TT 512
#define CC 128
#define HH 1024
#define GBLK 148
#define GW 7

typedef unsigned long long ull;

// ---------------- f32x2 helpers (decoder kernels) ----------------
__device__ __forceinline__ ull dup2(float x)
{
    ull r;
    asm("mov.b64 %0, {%1, %1};" : "=l"(r) : "f"(x));
    return r;
}
__device__ __forceinline__ ull ffma2(ull a, ull b, ull c)
{
    ull d;
    asm("fma.rn.f32x2 %0, %1, %2, %3;" : "=l"(d) : "l"(a), "l"(b), "l"(c));
    return d;
}
__device__ __forceinline__ float2 unpk2(ull v)
{
    float2 f;
    asm("mov.b64 {%0, %1}, %2;" : "=f"(f.x), "=f"(f.y) : "l"(v));
    return f;
}

// ---------------- static scratch ----------------
__device__ float g_xg[BB * TT * 3 * HH];
__device__ float g_h[2][BB * HH];
__device__ float g_emb2[BB * CC * TT * 8];
__device__ float g_x3[BB * CC * TT * 8];
__device__ float g_e3x[BB * CC * TT * 16];
__device__ float g_x2[BB * CC * TT * 16];
__device__ float g_e2x[BB * CC * TT * 32];
__device__ float g_x1[BB * CC * TT * 32];
__device__ float g_e1x[BB * CC * TT * 64];
__device__ float g_wtT3[3 * CC * CC];
__device__ float g_wtT2[3 * CC * CC];
__device__ float g_wtT1[3 * CC * CC];
__device__ unsigned short g_Ah[BB * TT * HH];
__device__ unsigned short g_Al[BB * TT * HH];
__device__ unsigned short g_Wh[3 * HH * HH];
__device__ unsigned short g_Wl[3 * HH * HH];
__device__ unsigned g_bar_count;
__device__ unsigned g_bar_gen;

// ---------------- barrier state reset (per launch) ----------------
__global__ void k_reset()
{
    if (threadIdx.x == 0) { g_bar_count = 0; g_bar_gen = 0; }
}

// ---------------- acquire/release grid barrier ----------------
__device__ __forceinline__ void grid_barrier(unsigned my_gen)
{
    __syncthreads();
    if (threadIdx.x == 0) {
        unsigned arr;
        asm volatile("atom.add.release.gpu.u32 %0, [%1], 1;"
                     : "=r"(arr) : "l"(&g_bar_count) : "memory");
        if (arr == GBLK - 1) {
            g_bar_count = 0;
            asm volatile("st.release.gpu.u32 [%0], %1;"
                         :: "l"(&g_bar_gen), "r"(my_gen) : "memory");
        } else {
            unsigned cur;
            do {
                asm volatile("ld.acquire.gpu.u32 %0, [%1];"
                             : "=r"(cur) : "l"(&g_bar_gen) : "memory");
            } while ((int)(cur - my_gen) < 0);
        }
    }
    __syncthreads();
}

// ---------------- bf16 hi/lo split: src fp32 -> (hi, lo) bf16 ----------------
__global__ __launch_bounds__(256) void k_split(const float4* __restrict__ src,
                                               ushort4* __restrict__ hi,
                                               ushort4* __restrict__ lo,
                                               int n4)
{
    int i = blockIdx.x * 256 + threadIdx.x;
    if (i >= n4) return;
    float4 v = src[i];
    float f[4] = { v.x, v.y, v.z, v.w };
    unsigned short h[4], l[4];
#pragma unroll
    for (int q = 0; q < 4; ++q) {
        __nv_bfloat16 bh = __float2bfloat16(f[q]);
        float r = f[q] - __bfloat162float(bh);
        __nv_bfloat16 bl = __float2bfloat16(r);
        h[q] = *(unsigned short*)&bh;
        l[q] = *(unsigned short*)&bl;
    }
    hi[i] = make_ushort4(h[0], h[1], h[2], h[3]);
    lo[i] = make_ushort4(l[0], l[1], l[2], l[3]);
}

// ---------------- mma helpers (sm_80-baseline PTX, works on sm_103) ----------
__device__ __forceinline__ unsigned smem_u32(const void* p)
{
    unsigned a;
    asm("{ .reg .u64 t; cvta.to.shared.u64 t, %1; cvt.u32.u64 %0, t; }"
        : "=r"(a) : "l"(p));
    return a;
}
__device__ __forceinline__ void ldsm4(unsigned* r, unsigned addr)
{
    asm volatile("ldmatrix.sync.aligned.m8n8.x4.shared.b16 {%0,%1,%2,%3}, [%4];"
        : "=r"(r[0]), "=r"(r[1]), "=r"(r[2]), "=r"(r[3]) : "r"(addr));
}
__device__ __forceinline__ void ldsm2(unsigned* r, unsigned addr)
{
    asm volatile("ldmatrix.sync.aligned.m8n8.x2.shared.b16 {%0,%1}, [%2];"
        : "=r"(r[0]), "=r"(r[1]) : "r"(addr));
}
__device__ __forceinline__ void mma16816(float* d, const unsigned* a, const unsigned* b)
{
    asm volatile("mma.sync.aligned.m16n8k16.row.col.f32.bf16.bf16.f32 "
        "{%0,%1,%2,%3}, {%4,%5,%6,%7}, {%8,%9}, {%0,%1,%2,%3};"
        : "+f"(d[0]), "+f"(d[1]), "+f"(d[2]), "+f"(d[3])
        : "r"(a[0]), "r"(a[1]), "r"(a[2]), "r"(a[3]), "r"(b[0]), "r"(b[1]));
}

// ---------------- xg = emb @ Wih^T + bih : mma.sync split-bf16 ----------------
// block tile 128(M) x 64(N), 8 warps = 4m x 2n, warp tile 32x32, K chunk 32
__global__ __launch_bounds__(256) void k_xg_mma(const float* __restrict__ bias)
{
    __shared__ __align__(16) unsigned short sAh[128][40];
    __shared__ __align__(16) unsigned short sAl[128][40];
    __shared__ __align__(16) unsigned short sWh[64][40];
    __shared__ __align__(16) unsigned short sWl[64][40];
    int tid = threadIdx.x, lane = tid & 31, wid = tid >> 5;
    int wm = wid >> 1, wn = wid & 1;
    int m0 = blockIdx.y * 128, n0 = blockIdx.x * 64;

    float acc[2][4][4];
#pragma unroll
    for (int mi = 0; mi < 2; ++mi)
#pragma unroll
        for (int ni = 0; ni < 4; ++ni)
#pragma unroll
            for (int q = 0; q < 4; ++q) acc[mi][ni][q] = 0.f;

    for (int kc = 0; kc < HH; kc += 32) {
        __syncthreads();
#pragma unroll
        for (int i = 0; i < 6; ++i) {
            int idx = tid + i * 256;     // 0..1535
            const uint4* src;
            unsigned short* dst;
            if (idx < 512) {
                int row = idx >> 2, c8 = (idx & 3) * 8;
                src = (const uint4*)&g_Ah[(size_t)(m0 + row) * HH + kc + c8];
                dst = &sAh[row][c8];
            } else if (idx < 1024) {
                int e = idx - 512;
                int row = e >> 2, c8 = (e & 3) * 8;
                src = (const uint4*)&g_Al[(size_t)(m0 + row) * HH + kc + c8];
                dst = &sAl[row][c8];
            } else if (idx < 1280) {
                int e = idx - 1024;
                int row = e >> 2, c8 = (e & 3) * 8;
                src = (const uint4*)&g_Wh[(size_t)(n0 + row) * HH + kc + c8];
                dst = &sWh[row][c8];
            } else {
                int e = idx - 1280;
                int row = e >> 2, c8 = (e & 3) * 8;
                src = (const uint4*)&g_Wl[(size_t)(n0 + row) * HH + kc + c8];
                dst = &sWl[row][c8];
            }
            *(uint4*)dst = *src;
        }
        __syncthreads();

#pragma unroll
        for (int ks = 0; ks < 2; ++ks) {
            int k0 = ks * 16;
            unsigned ah[2][4], al[2][4];
#pragma unroll
            for (int mi = 0; mi < 2; ++mi) {
                int m = wm * 32 + mi * 16 + (lane & 15);
                int kk = k0 + (lane >> 4) * 8;
                ldsm4(ah[mi], smem_u32(&sAh[m][kk]));
                ldsm4(al[mi], smem_u32(&sAl[m][kk]));
            }
            unsigned bh[4][2], bl[4][2];
#pragma unroll
            for (int ni = 0; ni < 4; ++ni) {
                int r = lane & 15;
                int n = wn * 32 + ni * 8 + (r & 7);
                int kk = k0 + (r >> 3) * 8;
                ldsm2(bh[ni], smem_u32(&sWh[n][kk]));
                ldsm2(bl[ni], smem_u32(&sWl[n][kk]));
            }
#pragma unroll
            for (int mi = 0; mi < 2; ++mi)
#pragma unroll
                for (int ni = 0; ni < 4; ++ni) {
                    mma16816(acc[mi][ni], ah[mi], bh[ni]);
                    mma16816(acc[mi][ni], ah[mi], bl[ni]);
                    mma16816(acc[mi][ni], al[mi], bh[ni]);
                }
        }
    }
    // epilogue: d0,d1 -> (row, col/col+1); d2,d3 -> (row+8, ...)
    int gr = lane >> 2, gc = (lane & 3) * 2;
#pragma unroll
    for (int mi = 0; mi < 2; ++mi)
#pragma unroll
        for (int ni = 0; ni < 4; ++ni) {
            int m = m0 + wm * 32 + mi * 16 + gr;
            int n = n0 + wn * 32 + ni * 8 + gc;
            float b0 = bias[n], b1 = bias[n + 1];
            float2 v0 = { acc[mi][ni][0] + b0, acc[mi][ni][1] + b1 };
            float2 v1 = { acc[mi][ni][2] + b0, acc[mi][ni][3] + b1 };
            *(float2*)&g_xg[(size_t)m * (3 * HH) + n] = v0;
            *(float2*)&g_xg[(size_t)(m + 8) * (3 * HH) + n] = v1;
        }
}

// ---------------- persistent GRU: 148 blocks x 224 thr, scalar reg Whh --------
__global__ __launch_bounds__(224) void k_gru(const float* __restrict__ h0,
                                             const float* __restrict__ Whh,
                                             const float* __restrict__ bhh,
                                             float* __restrict__ outHT)
{
    __shared__ __align__(16) float hs[BB][HH];
    int tid = threadIdx.x;
    int lane = tid & 31, wid = tid >> 5;
    int j = blockIdx.x * GW + wid;
    bool valid = (j < HH);
    int c = j & 127, f = j >> 7;

    float4 wr4[8], wz4[8], wn4[8];
    float br = 0.f, bz = 0.f, bn = 0.f;
    if (valid) {
        const float* wr = Whh + (size_t)j * HH;
        const float* wz = Whh + (size_t)(j + HH) * HH;
        const float* wn = Whh + (size_t)(j + 2 * HH) * HH;
#pragma unroll
        for (int i = 0; i < 8; ++i) {
            wr4[i] = *(const float4*)&wr[i * 128 + lane * 4];
            wz4[i] = *(const float4*)&wz[i * 128 + lane * 4];
            wn4[i] = *(const float4*)&wn[i * 128 + lane * 4];
        }
        br = bhh[j]; bz = bhh[j + HH]; bn = bhh[j + 2 * HH];
    } else {
#pragma unroll
        for (int i = 0; i < 8; ++i) {
            wr4[i] = make_float4(0, 0, 0, 0);
            wz4[i] = make_float4(0, 0, 0, 0);
            wn4[i] = make_float4(0, 0, 0, 0);
        }
    }

    unsigned my_gen = 0;
    {
        int i = blockIdx.x * 224 + tid;
        if (i < BB * HH) g_h[0][i] = h0[i];
    }
    ++my_gen;
    grid_barrier(my_gen);

    for (int t = 0; t < TT; ++t) {
        const float4* hp = (const float4*)&g_h[t & 1][0];
        float* hw = &g_h[(t + 1) & 1][0];
#pragma unroll
        for (int i = 0; i < 10; ++i) {
            int idx4 = tid + i * 224;
            if (idx4 < 2048) {
                float4 v = hp[idx4];
                *(float4*)&hs[idx4 >> 8][(idx4 & 255) * 4] = v;
            }
        }
        __syncthreads();

        float xr = 0.f, xz = 0.f, xn = 0.f;
        if (valid && lane < 8) {
            const float* xgp = g_xg + (size_t)(lane * TT + t) * (3 * HH);
            xr = xgp[j]; xz = xgp[j + HH]; xn = xgp[j + 2 * HH];
        }

        float accR[8], accZ[8], accN[8];
#pragma unroll
        for (int b = 0; b < 8; ++b) { accR[b] = 0.f; accZ[b] = 0.f; accN[b] = 0.f; }

        if (valid) {
#pragma unroll
            for (int i = 0; i < 8; ++i) {
                float4 a = wr4[i], b4 = wz4[i], c4 = wn4[i];
#pragma unroll
                for (int b = 0; b < 8; ++b) {
                    float4 h4 = *(const float4*)&hs[b][i * 128 + lane * 4];
                    accR[b] = fmaf(a.x, h4.x, accR[b]);
                    accR[b] = fmaf(a.y, h4.y, accR[b]);
                    accR[b] = fmaf(a.z, h4.z, accR[b]);
                    accR[b] = fmaf(a.w, h4.w, accR[b]);
                    accZ[b] = fmaf(b4.x, h4.x, accZ[b]);
                    accZ[b] = fmaf(b4.y, h4.y, accZ[b]);
                    accZ[b] = fmaf(b4.z, h4.z, accZ[b]);
                    accZ[b] = fmaf(b4.w, h4.w, accZ[b]);
                    accN[b] = fmaf(c4.x, h4.x, accN[b]);
                    accN[b] = fmaf(c4.y, h4.y, accN[b]);
                    accN[b] = fmaf(c4.z, h4.z, accN[b]);
                    accN[b] = fmaf(c4.w, h4.w, accN[b]);
                }
            }
#pragma unroll
            for (int b = 0; b < 8; ++b)
#pragma unroll
                for (int off = 16; off; off >>= 1) {
                    accR[b] += __shfl_xor_sync(0xffffffffu, accR[b], off);
                    accZ[b] += __shfl_xor_sync(0xffffffffu, accZ[b], off);
                    accN[b] += __shfl_xor_sync(0xffffffffu, accN[b], off);
                }
            if (lane < 8) {
                int b = lane;
                float r = 1.f / (1.f + __expf(-(xr + accR[b] + br)));
                float z = 1.f / (1.f + __expf(-(xz + accZ[b] + bz)));
                float n = tanhf(xn + r * (accN[b] + bn));
                float hnew = (1.f - z) * n + z * hs[b][j];
                hw[b * HH + j] = hnew;
                g_emb2[((size_t)(b * CC + c) * TT + t) * 8 + f] = hnew;
                if (t == TT - 1) outHT[b * HH + j] = hnew;
            }
        }
        ++my_gen;
        grid_barrier(my_gen);
    }
}

// ---------------- 1x1 conv over channels + bias + skip, f32x2 ----------------
__global__ __launch_bounds__(256) void k_pconv(float* __restrict__ out,
                                               const float* __restrict__ in,
                                               const float* __restrict__ W,
                                               const float* __restrict__ bias,
                                               const float* __restrict__ skip,
                                               int TF)
{
    __shared__ __align__(16) float Xs[128][64];
    __shared__ __align__(16) float Ws[16][128];
    int tid = threadIdx.x;
    int tx = tid & 15, ty = tid >> 4;
    int b = blockIdx.y;
    int p0 = blockIdx.x * 64;

#pragma unroll
    for (int i = 0; i < 8; ++i) {
        int e4 = tid + i * 256;
        int ch = e4 >> 4, pq = (e4 & 15) << 2;
        *(float4*)&Xs[ch][pq] = *(const float4*)&in[(size_t)(b * CC + ch) * TF + p0 + pq];
    }
    ull acc2[4][4];
#pragma unroll
    for (int p = 0; p < 4; ++p)
#pragma unroll
        for (int q = 0; q < 4; ++q) acc2[p][q] = 0ull;

    for (int kb = 0; kb < CC; kb += 16) {
#pragma unroll
        for (int i = 0; i < 2; ++i) {
            int e4 = tid * 2 + i;
            int oc = e4 >> 2, k4 = (e4 & 3) << 2;
            float4 v = *(const float4*)&W[oc * CC + kb + k4];
            Ws[k4 + 0][oc] = v.x; Ws[k4 + 1][oc] = v.y;
            Ws[k4 + 2][oc] = v.z; Ws[k4 + 3][oc] = v.w;
        }
        __syncthreads();
#pragma unroll
        for (int kk = 0; kk < 16; ++kk) {
            float4 xv = *(const float4*)&Xs[kb + kk][tx * 4];
            ull dx[4];
            dx[0] = dup2(xv.x); dx[1] = dup2(xv.y);
            dx[2] = dup2(xv.z); dx[3] = dup2(xv.w);
            ull wp[4];
#pragma unroll
            for (int p = 0; p < 4; ++p)
                wp[p] = *(const ull*)&Ws[kk][ty * 8 + 2 * p];
#pragma unroll
            for (int p = 0; p < 4; ++p)
#pragma unroll
                for (int q = 0; q < 4; ++q)
                    acc2[p][q] = ffma2(wp[p], dx[q], acc2[p][q]);
        }
        __syncthreads();
    }
#pragma unroll
    for (int p = 0; p < 4; ++p) {
        int oc0 = ty * 8 + 2 * p, oc1 = oc0 + 1;
        float2 u0 = unpk2(acc2[p][0]), u1 = unpk2(acc2[p][1]);
        float2 u2 = unpk2(acc2[p][2]), u3 = unpk2(acc2[p][3]);
        size_t i0 = (size_t)(b * CC + oc0) * TF + p0 + tx * 4;
        size_t i1 = (size_t)(b * CC + oc1) * TF + p0 + tx * 4;
        float bv0 = bias[oc0], bv1 = bias[oc1];
        float4 s0 = *(const float4*)&skip[i0];
        float4 s1 = *(const float4*)&skip[i1];
        float4 o0, o1;
        o0.x = u0.x + bv0 + s0.x; o0.y = u1.x + bv0 + s0.y;
        o0.z = u2.x + bv0 + s0.z; o0.w = u3.x + bv0 + s0.w;
        o1.x = u0.y + bv1 + s1.x; o1.y = u1.y + bv1 + s1.y;
        o1.z = u2.y + bv1 + s1.z; o1.w = u3.y + bv1 + s1.w;
        *(float4*)&out[i0] = o0;
        *(float4*)&out[i1] = o1;
    }
}

// ---------------- weight transpose for convt ----------------
__global__ __launch_bounds__(256) void k_wtT(const float* __restrict__ src,
                                             float* __restrict__ dst)
{
    int i = blockIdx.x * 256 + threadIdx.x;
    if (i < 3 * CC * CC) {
        int oc = i & 127, ic = (i >> 7) & 127, tap = i >> 14;
        dst[i] = src[(oc * CC + ic) * 3 + tap];
    }
}

// ---------------- transposed conv over freq (k=3,s=2) + ReLU, f32x2 ----------
__global__ __launch_bounds__(128) void k_convt(float* __restrict__ out,
                                               const float* __restrict__ in,
                                               const float* __restrict__ wT,
                                               const float* __restrict__ bias,
                                               int Fin, int TF)
{
    __shared__ __align__(16) float Xs[128][36];
    __shared__ __align__(16) float Ws[3][16][128];
    int tid = threadIdx.x;
    int tx = tid & 7, ty = tid >> 3;
    int b = blockIdx.y;
    int p0 = blockIdx.x * 32;

#pragma unroll
    for (int i = 0; i < 8; ++i) {
        int e4 = tid + i * 128;
        int ch = e4 >> 3, pq = (e4 & 7) << 2;
        *(float4*)&Xs[ch][pq] = *(const float4*)&in[(size_t)(b * CC + ch) * TF + p0 + pq];
    }
    int p_ = tx * 4;
    bool sh[4];
#pragma unroll
    for (int jj = 0; jj < 4; ++jj) sh[jj] = (((p_ + jj) & (Fin - 1)) != Fin - 1);

    ull ae2[4][4], ao2[4][4];
#pragma unroll
    for (int p = 0; p < 4; ++p)
#pragma unroll
        for (int q = 0; q < 4; ++q) { ae2[p][q] = 0ull; ao2[p][q] = 0ull; }

    for (int kb = 0; kb < CC; kb += 16) {
        __syncthreads();
#pragma unroll
        for (int i = 0; i < 12; ++i) {
            int idx = tid + i * 128;
            int tap = idx / 512, rem = idx & 511;
            int kkk = rem >> 5, oc4 = (rem & 31) << 2;
            *(float4*)&Ws[tap][kkk][oc4] =
                *(const float4*)&wT[(tap * CC + kb + kkk) * CC + oc4];
        }
        __syncthreads();
#pragma unroll
        for (int kk = 0; kk < 16; ++kk) {
            const float* xrow = &Xs[kb + kk][0];
            float4 xv = *(const float4*)&xrow[p_];
            float xnext = xrow[p_ + 4];
            ull dx[4], dxs[4];
            dx[0] = dup2(xv.x); dx[1] = dup2(xv.y);
            dx[2] = dup2(xv.z); dx[3] = dup2(xv.w);
            dxs[0] = dup2(sh[0] ? xv.y : 0.f);
            dxs[1] = dup2(sh[1] ? xv.z : 0.f);
            dxs[2] = dup2(sh[2] ? xv.w : 0.f);
            dxs[3] = dup2(sh[3] ? xnext : 0.f);
            ull w0p[4], w1p[4], w2p[4];
#pragma unroll
            for (int p = 0; p < 4; ++p) {
                w0p[p] = *(const ull*)&Ws[0][kk][ty * 8 + 2 * p];
                w1p[p] = *(const ull*)&Ws[1][kk][ty * 8 + 2 * p];
                w2p[p] = *(const ull*)&Ws[2][kk][ty * 8 + 2 * p];
            }
#pragma unroll
            for (int p = 0; p < 4; ++p)
#pragma unroll
                for (int q = 0; q < 4; ++q) {
                    ae2[p][q] = ffma2(w1p[p], dx[q], ae2[p][q]);
                    ao2[p][q] = ffma2(w0p[p], dx[q], ao2[p][q]);
                    ao2[p][q] = ffma2(w2p[p], dxs[q], ao2[p][q]);
                }
        }
    }
    int TF2 = TF * 2;
#pragma unroll
    for (int p = 0; p < 4; ++p) {
        int oc0 = ty * 8 + 2 * p, oc1 = oc0 + 1;
        float bv0 = bias[oc0], bv1 = bias[oc1];
#pragma unroll
        for (int q = 0; q < 4; ++q) {
            int pp = p0 + p_ + q;
            float2 e = unpk2(ae2[p][q]);
            float2 o = unpk2(ao2[p][q]);
            float2 r0, r1;
            r0.x = fmaxf(e.x + bv0, 0.f); r0.y = fmaxf(o.x + bv0, 0.f);
            r1.x = fmaxf(e.y + bv1, 0.f); r1.y = fmaxf(o.y + bv1, 0.f);
            *(float2*)&out[(size_t)(b * CC + oc0) * TF2 + 2 * pp] = r0;
            *(float2*)&out[(size_t)(b * CC + oc1) * TF2 + 2 * pp] = r1;
        }
    }
}

// ---------------- final: pre = w0p@e0 + b0p + e1x ; m = sigmoid(conv3(pre)) ----
__global__ __launch_bounds__(256) void k_final(const float* __restrict__ e0,
                                               const float* __restrict__ W,
                                               const float* __restrict__ bias,
                                               const float* __restrict__ w0o,
                                               const float* __restrict__ b0o,
                                               float* __restrict__ outm)
{
    __shared__ __align__(16) float Xs[128][64];
    __shared__ __align__(16) float Ws[16][128];
    __shared__ float wo[128][3];
    const int TF = TT * 64;
    int tid = threadIdx.x;
    int tx = tid & 15, ty = tid >> 4;
    int b = blockIdx.y, t = blockIdx.x;
    int p0 = t * 64;

#pragma unroll
    for (int i = 0; i < 8; ++i) {
        int e4 = tid + i * 256;
        int ch = e4 >> 4, pq = (e4 & 15) << 2;
        *(float4*)&Xs[ch][pq] = *(const float4*)&e0[(size_t)(b * CC + ch) * TF + p0 + pq];
    }
    for (int i = tid; i < 384; i += 256) wo[i / 3][i % 3] = w0o[i];

    ull acc2[4][4];
#pragma unroll
    for (int p = 0; p < 4; ++p)
#pragma unroll
        for (int q = 0; q < 4; ++q) acc2[p][q] = 0ull;

    for (int kb = 0; kb < CC; kb += 16) {
#pragma unroll
        for (int i = 0; i < 2; ++i) {
            int e4 = tid * 2 + i;
            int oc = e4 >> 2, k4 = (e4 & 3) << 2;
            float4 v = *(const float4*)&W[oc * CC + kb + k4];
            Ws[k4 + 0][oc] = v.x; Ws[k4 + 1][oc] = v.y;
            Ws[k4 + 2][oc] = v.z; Ws[k4 + 3][oc] = v.w;
        }
        __syncthreads();
#pragma unroll
        for (int kk = 0; kk < 16; ++kk) {
            float4 xv = *(const float4*)&Xs[kb + kk][tx * 4];
            ull dx[4];
            dx[0] = dup2(xv.x); dx[1] = dup2(xv.y);
            dx[2] = dup2(xv.z); dx[3] = dup2(xv.w);
            ull wp[4];
#pragma unroll
            for (int p = 0; p < 4; ++p)
                wp[p] = *(const ull*)&Ws[kk][ty * 8 + 2 * p];
#pragma unroll
            for (int p = 0; p < 4; ++p)
#pragma unroll
                for (int q = 0; q < 4; ++q)
                    acc2[p][q] = ffma2(wp[p], dx[q], acc2[p][q]);
        }
        __syncthreads();
    }
#pragma unroll
    for (int p = 0; p < 4; ++p) {
        int oc0 = ty * 8 + 2 * p, oc1 = oc0 + 1;
        float bv0 = bias[oc0], bv1 = bias[oc1];
        float2 u0 = unpk2(acc2[p][0]), u1 = unpk2(acc2[p][1]);
        float2 u2 = unpk2(acc2[p][2]), u3 = unpk2(acc2[p][3]);
        int pq = tx * 4;
        Xs[oc0][pq + 0] = u0.x + bv0 + g_e1x[(size_t)(b * CC + oc0) * TF + p0 + pq + 0];
        Xs[oc0][pq + 1] = u1.x + bv0 + g_e1x[(size_t)(b * CC + oc0) * TF + p0 + pq + 1];
        Xs[oc0][pq + 2] = u2.x + bv0 + g_e1x[(size_t)(b * CC + oc0) * TF + p0 + pq + 2];
        Xs[oc0][pq + 3] = u3.x + bv0 + g_e1x[(size_t)(b * CC + oc0) * TF + p0 + pq + 3];
        Xs[oc1][pq + 0] = u0.y + bv1 + g_e1x[(size_t)(b * CC + oc1) * TF + p0 + pq + 0];
        Xs[oc1][pq + 1] = u1.y + bv1 + g_e1x[(size_t)(b * CC + oc1) * TF + p0 + pq + 1];
        Xs[oc1][pq + 2] = u2.y + bv1 + g_e1x[(size_t)(b * CC + oc1) * TF + p0 + pq + 2];
        Xs[oc1][pq + 3] = u3.y + bv1 + g_e1x[(size_t)(b * CC + oc1) * TF + p0 + pq + 3];
    }
    __syncthreads();
    int f = tid >> 2, q = tid & 3;
    float s = 0.f;
#pragma unroll 4
    for (int i = 0; i < 32; ++i) {
        int ch = q * 32 + i;
        float x0 = Xs[ch][f];
        float xm = (f > 0) ? Xs[ch][f - 1] : 0.f;
        float xp = (f < 63) ? Xs[ch][f + 1] : 0.f;
        s = fmaf(wo[ch][0], xm, s);
        s = fmaf(wo[ch][1], x0, s);
        s = fmaf(wo[ch][2], xp, s);
    }
    s += __shfl_down_sync(0xffffffffu, s, 1);
    s += __shfl_down_sync(0xffffffffu, s, 2);
    if (q == 0) outm[((size_t)b * TT + t) * 64 + f] = 1.f / (1.f + __expf(-(s + b0o[0])));
}

// ---------------------------------- launch ----------------------------------
extern "C" void kernel_launch(void* const* d_in, const int* in_sizes, int n_in,
                              void* d_out, int out_size)
{
    const float* emb   = (const float*)d_in[0];
    const float* e3    = (const float*)d_in[1];
    const float* e2    = (const float*)d_in[2];
    const float* e1    = (const float*)d_in[3];
    const float* e0    = (const float*)d_in[4];
    const float* h_erb = (const float*)d_in[5];
    const float* Wih   = (const float*)d_in[6];
    const float* Whh   = (const float*)d_in[7];
    const float* bih   = (const float*)d_in[8];
    const float* bhh   = (const float*)d_in[9];
    const float* w3p   = (const float*)d_in[10];
    const float* b3p   = (const float*)d_in[11];
    const float* w2p   = (const float*)d_in[12];
    const float* b2p   = (const float*)d_in[13];
    const float* w1p   = (const float*)d_in[14];
    const float* b1p   = (const float*)d_in[15];
    const float* w0p   = (const float*)d_in[16];
    const float* b0p   = (const float*)d_in[17];
    const float* wt3   = (const float*)d_in[18];
    const float* bt3   = (const float*)d_in[19];
    const float* wt2   = (const float*)d_in[20];
    const float* bt2   = (const float*)d_in[21];
    const float* wt1   = (const float*)d_in[22];
    const float* bt1   = (const float*)d_in[23];
    const float* w0o   = (const float*)d_in[24];
    const float* b0o   = (const float*)d_in[25];
    float* out = (float*)d_out;

    float* gx3;  cudaGetSymbolAddress((void**)&gx3,  g_x3);
    float* ge3x; cudaGetSymbolAddress((void**)&ge3x, g_e3x);
    float* gx2;  cudaGetSymbolAddress((void**)&gx2,  g_x2);
    float* ge2x; cudaGetSymbolAddress((void**)&ge2x, g_e2x);
    float* gx1;  cudaGetSymbolAddress((void**)&gx1,  g_x1);
    float* ge1x; cudaGetSymbolAddress((void**)&ge1x, g_e1x);
    float* gemb2;cudaGetSymbolAddress((void**)&gemb2,g_emb2);
    float* gw3;  cudaGetSymbolAddress((void**)&gw3,  g_wtT3);
    float* gw2;  cudaGetSymbolAddress((void**)&gw2,  g_wtT2);
    float* gw1;  cudaGetSymbolAddress((void**)&gw1,  g_wtT1);
    void *pAh, *pAl, *pWh, *pWl;
    cudaGetSymbolAddress(&pAh, g_Ah);
    cudaGetSymbolAddress(&pAl, g_Al);
    cudaGetSymbolAddress(&pWh, g_Wh);
    cudaGetSymbolAddress(&pWl, g_Wl);

    // launch order chosen so ncu (-s 5 -c 1) profiles k_xg_mma (index 5)
    k_wtT<<<192, 256>>>(wt3, gw3);                                  // 0
    k_wtT<<<192, 256>>>(wt2, gw2);                                  // 1
    k_wtT<<<192, 256>>>(wt1, gw1);                                  // 2
    k_split<<<4096, 256>>>((const float4*)emb,
                           (ushort4*)pAh, (ushort4*)pAl, 1048576);  // 3
    k_split<<<3072, 256>>>((const float4*)Wih,
                           (ushort4*)pWh, (ushort4*)pWl, 786432);   // 4
    k_xg_mma<<<dim3(48, 32), 256>>>(bih);                           // 5
    k_reset<<<1, 32>>>();                                           // 6
    k_gru<<<GBLK, 224>>>(h_erb, Whh, bhh, out + BB * TT * 64);      // 7

    k_pconv<<<dim3(64, 8),  256>>>(gx3, e3, w3p, b3p, gemb2, TT * 8);
    k_convt<<<dim3(128, 8), 128>>>(ge3x, gx3, gw3, bt3, 8, TT * 8);

    k_pconv<<<dim3(128, 8), 256>>>(gx2, e2, w2p, b2p, ge3x, TT * 16);
    k_convt<<<dim3(256, 8), 128>>>(ge2x, gx2, gw2, bt2, 16, TT * 16);

    k_pconv<<<dim3(256, 8), 256>>>(gx1, e1, w1p, b1p, ge2x, TT * 32);
    k_convt<<<dim3(512, 8), 128>>>(ge1x, gx1, gw1, bt1, 32, TT * 32);

    k_final<<<dim3(512, 8), 256>>>(e0, w0p, b0p, w0o, b0o, out);
}